// round 1
// baseline (speedup 1.0000x reference)
#include <cuda_runtime.h>
#include <math.h>

#define Nn 100000
#define Ee 1600000
#define Dd 128
#define Ll 3
#define CAPB 96
#define MAX_OV 8192
#define NDTOT (Nn * Dd)

// ---------------- device scratch (no allocations allowed) ----------------
static __device__ float A_buf[NDTOT];                 // lin1(y) per node
static __device__ float H_buf[NDTOT];                 // running h accumulator
static __device__ int   cnt_buf[Nn];                  // in-degree (int)
static __device__ int   bucket_buf[Nn * CAPB];        // CSR-ish buckets of src ids
static __device__ int   ov_src[MAX_OV];
static __device__ int   ov_dst[MAX_OV];
static __device__ int   ov_cnt;
static __device__ int   g_is64;
static __device__ double g_sum, g_sumsq;

// ---------------- init: zero counters + detect edge dtype ----------------
__global__ void init_kernel(const int* __restrict__ ei) {
    int i = blockIdx.x * blockDim.x + threadIdx.x;
    if (i < Nn) cnt_buf[i] = 0;
    if (i == 0) {
        ov_cnt = 0;
        // int64 little-endian with values < 2^31 => every odd int32 word is 0
        int all0 = 1;
        for (int k = 0; k < 128; k++) {
            if (ei[2 * k + 1] != 0) { all0 = 0; break; }
        }
        g_is64 = all0;
    }
}

__device__ __forceinline__ int fetch_idx(const int* __restrict__ ei, int pos, int is64) {
    return is64 ? ei[2 * pos] : ei[pos];
}

// ---------------- build bucketed adjacency (per-launch, deterministic) ----
__global__ void build_csr(const int* __restrict__ ei) {
    int e = blockIdx.x * blockDim.x + threadIdx.x;
    if (e >= Ee) return;
    int is64 = g_is64;
    int src = fetch_idx(ei, e, is64);
    int dst = fetch_idx(ei, Ee + e, is64);
    int pos = atomicAdd(&cnt_buf[dst], 1);
    if (pos < CAPB) {
        bucket_buf[(size_t)dst * CAPB + pos] = src;
    } else {
        int o = atomicAdd(&ov_cnt, 1);
        if (o < MAX_OV) { ov_src[o] = src; ov_dst[o] = dst; }
    }
}

// ---------------- GEMM A = y@W1 + b1  (128x128 block tile, fp32) ---------
__global__ void __launch_bounds__(256) gemm_a(const float* __restrict__ Y,
                                              const float* __restrict__ W,
                                              const float* __restrict__ bias) {
    __shared__ float ys[16][136];   // transposed y tile [k][row], padded
    __shared__ float ws[16][128];   // W tile [k][col]

    int tid = threadIdx.x;
    int base = blockIdx.x * 128;
    int r0 = (tid >> 4) * 8;
    int c0 = (tid & 15) * 8;

    float acc[8][8];
#pragma unroll
    for (int i = 0; i < 8; i++)
#pragma unroll
        for (int j = 0; j < 8; j++) acc[i][j] = 0.f;

    for (int k0 = 0; k0 < 128; k0 += 16) {
#pragma unroll
        for (int p = 0; p < 2; p++) {
            int s = tid + p * 256;
            int r = s >> 2;
            int c = (s & 3) * 4;
            float4 v = make_float4(0.f, 0.f, 0.f, 0.f);
            int row = base + r;
            if (row < Nn)
                v = *reinterpret_cast<const float4*>(Y + (size_t)row * 128 + k0 + c);
            ys[c + 0][r] = v.x; ys[c + 1][r] = v.y;
            ys[c + 2][r] = v.z; ys[c + 3][r] = v.w;
        }
#pragma unroll
        for (int p = 0; p < 2; p++) {
            int s = tid + p * 256;
            int kk = s >> 5;
            int cc = (s & 31) * 4;
            *reinterpret_cast<float4*>(&ws[kk][cc]) =
                *reinterpret_cast<const float4*>(W + (size_t)(k0 + kk) * 128 + cc);
        }
        __syncthreads();
#pragma unroll
        for (int kk = 0; kk < 16; kk++) {
            float yf[8], wf[8];
            *reinterpret_cast<float4*>(&yf[0]) = *reinterpret_cast<const float4*>(&ys[kk][r0]);
            *reinterpret_cast<float4*>(&yf[4]) = *reinterpret_cast<const float4*>(&ys[kk][r0 + 4]);
            *reinterpret_cast<float4*>(&wf[0]) = *reinterpret_cast<const float4*>(&ws[kk][c0]);
            *reinterpret_cast<float4*>(&wf[4]) = *reinterpret_cast<const float4*>(&ws[kk][c0 + 4]);
#pragma unroll
            for (int i = 0; i < 8; i++)
#pragma unroll
                for (int j = 0; j < 8; j++) acc[i][j] += yf[i] * wf[j];
        }
        __syncthreads();
    }

    float bv[8];
    *reinterpret_cast<float4*>(&bv[0]) = *reinterpret_cast<const float4*>(bias + c0);
    *reinterpret_cast<float4*>(&bv[4]) = *reinterpret_cast<const float4*>(bias + c0 + 4);
#pragma unroll
    for (int i = 0; i < 8; i++) {
        int row = base + r0 + i;
        if (row < Nn) {
            float4 o0 = make_float4(acc[i][0] + bv[0], acc[i][1] + bv[1],
                                    acc[i][2] + bv[2], acc[i][3] + bv[3]);
            float4 o1 = make_float4(acc[i][4] + bv[4], acc[i][5] + bv[5],
                                    acc[i][6] + bv[6], acc[i][7] + bv[7]);
            *reinterpret_cast<float4*>(A_buf + (size_t)row * 128 + c0)     = o0;
            *reinterpret_cast<float4*>(A_buf + (size_t)row * 128 + c0 + 4) = o1;
        }
    }
}

// ------- GEMM H = y@W3 + b3 - deg * (y@W2)  (fused dual accumulator) ------
__global__ void __launch_bounds__(256) gemm_h(const float* __restrict__ Y,
                                              const float* __restrict__ W2,
                                              const float* __restrict__ W3,
                                              const float* __restrict__ b3) {
    __shared__ float ys[16][136];
    __shared__ float ws2[16][128];
    __shared__ float ws3[16][128];

    int tid = threadIdx.x;
    int base = blockIdx.x * 128;
    int r0 = (tid >> 4) * 8;
    int c0 = (tid & 15) * 8;

    float acc2[8][8], acc3[8][8];
#pragma unroll
    for (int i = 0; i < 8; i++)
#pragma unroll
        for (int j = 0; j < 8; j++) { acc2[i][j] = 0.f; acc3[i][j] = 0.f; }

    for (int k0 = 0; k0 < 128; k0 += 16) {
#pragma unroll
        for (int p = 0; p < 2; p++) {
            int s = tid + p * 256;
            int r = s >> 2;
            int c = (s & 3) * 4;
            float4 v = make_float4(0.f, 0.f, 0.f, 0.f);
            int row = base + r;
            if (row < Nn)
                v = *reinterpret_cast<const float4*>(Y + (size_t)row * 128 + k0 + c);
            ys[c + 0][r] = v.x; ys[c + 1][r] = v.y;
            ys[c + 2][r] = v.z; ys[c + 3][r] = v.w;
        }
#pragma unroll
        for (int p = 0; p < 2; p++) {
            int s = tid + p * 256;
            int kk = s >> 5;
            int cc = (s & 31) * 4;
            *reinterpret_cast<float4*>(&ws2[kk][cc]) =
                *reinterpret_cast<const float4*>(W2 + (size_t)(k0 + kk) * 128 + cc);
            *reinterpret_cast<float4*>(&ws3[kk][cc]) =
                *reinterpret_cast<const float4*>(W3 + (size_t)(k0 + kk) * 128 + cc);
        }
        __syncthreads();
#pragma unroll
        for (int kk = 0; kk < 16; kk++) {
            float yf[8], wf2[8], wf3[8];
            *reinterpret_cast<float4*>(&yf[0])  = *reinterpret_cast<const float4*>(&ys[kk][r0]);
            *reinterpret_cast<float4*>(&yf[4])  = *reinterpret_cast<const float4*>(&ys[kk][r0 + 4]);
            *reinterpret_cast<float4*>(&wf2[0]) = *reinterpret_cast<const float4*>(&ws2[kk][c0]);
            *reinterpret_cast<float4*>(&wf2[4]) = *reinterpret_cast<const float4*>(&ws2[kk][c0 + 4]);
            *reinterpret_cast<float4*>(&wf3[0]) = *reinterpret_cast<const float4*>(&ws3[kk][c0]);
            *reinterpret_cast<float4*>(&wf3[4]) = *reinterpret_cast<const float4*>(&ws3[kk][c0 + 4]);
#pragma unroll
            for (int i = 0; i < 8; i++)
#pragma unroll
                for (int j = 0; j < 8; j++) {
                    acc2[i][j] += yf[i] * wf2[j];
                    acc3[i][j] += yf[i] * wf3[j];
                }
        }
        __syncthreads();
    }

    float bv[8];
    *reinterpret_cast<float4*>(&bv[0]) = *reinterpret_cast<const float4*>(b3 + c0);
    *reinterpret_cast<float4*>(&bv[4]) = *reinterpret_cast<const float4*>(b3 + c0 + 4);
#pragma unroll
    for (int i = 0; i < 8; i++) {
        int row = base + r0 + i;
        if (row < Nn) {
            float dg = (float)cnt_buf[row];
            float o[8];
#pragma unroll
            for (int j = 0; j < 8; j++) o[j] = acc3[i][j] + bv[j] - dg * acc2[i][j];
            *reinterpret_cast<float4*>(H_buf + (size_t)row * 128 + c0) =
                make_float4(o[0], o[1], o[2], o[3]);
            *reinterpret_cast<float4*>(H_buf + (size_t)row * 128 + c0 + 4) =
                make_float4(o[4], o[5], o[6], o[7]);
        }
    }
}

// ---------------- gather: H[v] += sum_{j->v} A[j]  (warp per node) --------
__global__ void gather_kernel() {
    if (blockIdx.x == 0 && threadIdx.x == 0) { g_sum = 0.0; g_sumsq = 0.0; }
    int gw = (blockIdx.x * blockDim.x + threadIdx.x) >> 5;
    int lane = threadIdx.x & 31;
    if (gw >= Nn) return;
    int c = cnt_buf[gw];
    if (c > CAPB) c = CAPB;
    const int* bk = bucket_buf + (size_t)gw * CAPB;
    float4 acc = make_float4(0.f, 0.f, 0.f, 0.f);
    int e = 0;
    for (; e + 1 < c; e += 2) {
        int s0 = bk[e], s1 = bk[e + 1];
        float4 a0 = __ldg(reinterpret_cast<const float4*>(A_buf + (size_t)s0 * 128) + lane);
        float4 a1 = __ldg(reinterpret_cast<const float4*>(A_buf + (size_t)s1 * 128) + lane);
        acc.x += a0.x + a1.x; acc.y += a0.y + a1.y;
        acc.z += a0.z + a1.z; acc.w += a0.w + a1.w;
    }
    if (e < c) {
        int s0 = bk[e];
        float4 a0 = __ldg(reinterpret_cast<const float4*>(A_buf + (size_t)s0 * 128) + lane);
        acc.x += a0.x; acc.y += a0.y; acc.z += a0.z; acc.w += a0.w;
    }
    float4* hp = reinterpret_cast<float4*>(H_buf + (size_t)gw * 128) + lane;
    float4 h = *hp;
    h.x += acc.x; h.y += acc.y; h.z += acc.z; h.w += acc.w;
    *hp = h;
}

// ---------------- overflow edges (expected count: 0) ----------------------
__global__ void overflow_fix() {
    int m = ov_cnt;
    if (m > MAX_OV) m = MAX_OV;
    int lane = threadIdx.x & 31;
    int w = threadIdx.x >> 5;
    for (int e = w; e < m; e += 8) {
        int src = ov_src[e], dst = ov_dst[e];
        const float* ap = A_buf + (size_t)src * 128;
        float* hp = H_buf + (size_t)dst * 128;
        for (int k = lane; k < 128; k += 32) atomicAdd(&hp[k], ap[k]);
    }
}

// ---------------- global mean / sumsq (double accumulation) ---------------
__global__ void reduce_stats() {
    int idx = blockIdx.x * blockDim.x + threadIdx.x;
    int stride = gridDim.x * blockDim.x;
    double s = 0.0, ss = 0.0;
    const float4* h4 = reinterpret_cast<const float4*>(H_buf);
    for (int i = idx; i < NDTOT / 4; i += stride) {
        float4 v = h4[i];
        s  += (double)v.x + (double)v.y + (double)v.z + (double)v.w;
        ss += (double)v.x * v.x + (double)v.y * v.y +
              (double)v.z * v.z + (double)v.w * v.w;
    }
#pragma unroll
    for (int o = 16; o > 0; o >>= 1) {
        s  += __shfl_down_sync(0xffffffffu, s, o);
        ss += __shfl_down_sync(0xffffffffu, ss, o);
    }
    __shared__ double sh[2][8];
    int lane = threadIdx.x & 31, w = threadIdx.x >> 5;
    if (lane == 0) { sh[0][w] = s; sh[1][w] = ss; }
    __syncthreads();
    if (threadIdx.x == 0) {
        double ts = 0.0, tss = 0.0;
        for (int i = 0; i < (int)(blockDim.x >> 5); i++) { ts += sh[0][i]; tss += sh[1][i]; }
        atomicAdd(&g_sum, ts);
        atomicAdd(&g_sumsq, tss);
    }
}

// --------- normalize + affine + leaky_relu + residual update --------------
__global__ void final_update(const float* __restrict__ lw, const float* __restrict__ lb,
                             const float* __restrict__ yin, float* __restrict__ yout) {
    double M = (double)NDTOT;
    double mean = g_sum / M;
    double var = g_sumsq / M - mean * mean;
    if (var < 0.0) var = 0.0;
    float inv = 1.0f / ((float)sqrt(var) + 1e-5f);
    float mf = (float)mean;

    int idx = blockIdx.x * blockDim.x + threadIdx.x;
    int stride = gridDim.x * blockDim.x;
    const float4* h4 = reinterpret_cast<const float4*>(H_buf);
    const float4* y4 = reinterpret_cast<const float4*>(yin);
    float4* o4 = reinterpret_cast<float4*>(yout);
    for (int i = idx; i < NDTOT / 4; i += stride) {
        int d = (i * 4) & 127;
        float4 w = *reinterpret_cast<const float4*>(lw + d);
        float4 b = *reinterpret_cast<const float4*>(lb + d);
        float4 h = h4[i];
        float4 y = y4[i];
        float t;
        float4 o;
        t = (h.x - mf) * inv; t = t * w.x + b.x; t = (t >= 0.f) ? t : 0.01f * t; o.x = y.x + t;
        t = (h.y - mf) * inv; t = t * w.y + b.y; t = (t >= 0.f) ? t : 0.01f * t; o.y = y.y + t;
        t = (h.z - mf) * inv; t = t * w.z + b.z; t = (t >= 0.f) ? t : 0.01f * t; o.z = y.z + t;
        t = (h.w - mf) * inv; t = t * w.w + b.w; t = (t >= 0.f) ? t : 0.01f * t; o.w = y.w + t;
        o4[i] = o;
    }
}

// ---------------------------------------------------------------------------
extern "C" void kernel_launch(void* const* d_in, const int* in_sizes, int n_in,
                              void* d_out, int out_size) {
    const float* y0 = (const float*)d_in[0];
    const int*   ei = (const int*)d_in[1];
    const float* W1 = (const float*)d_in[2];
    const float* b1 = (const float*)d_in[3];
    const float* W2 = (const float*)d_in[4];
    const float* W3 = (const float*)d_in[5];
    const float* b3 = (const float*)d_in[6];
    const float* lw = (const float*)d_in[7];
    const float* lb = (const float*)d_in[8];
    float* yout = (float*)d_out;

    (void)in_sizes; (void)n_in; (void)out_size;

    init_kernel<<<(Nn + 255) / 256, 256>>>(ei);
    build_csr<<<(Ee + 255) / 256, 256>>>(ei);

    const int gemm_blocks = (Nn + 127) / 128;   // 782
    for (int l = 0; l < Ll; l++) {
        const float* yin = (l == 0) ? y0 : yout;
        gemm_a<<<gemm_blocks, 256>>>(yin, W1 + (size_t)l * Dd * Dd, b1 + (size_t)l * Dd);
        gemm_h<<<gemm_blocks, 256>>>(yin, W2 + (size_t)l * Dd * Dd,
                                     W3 + (size_t)l * Dd * Dd, b3 + (size_t)l * Dd);
        gather_kernel<<<(Nn * 32 + 255) / 256, 256>>>();
        overflow_fix<<<1, 256>>>();
        reduce_stats<<<1024, 256>>>();
        final_update<<<1024, 256>>>(lw + (size_t)l * Dd, lb + (size_t)l * Dd, yin, yout);
    }
}